// round 2
// baseline (speedup 1.0000x reference)
#include <cuda_runtime.h>
#include <math.h>

#define B_ 8
#define L_ 4096
#define D_ 768
#define Y_ 2048

// ---- device scratch (no allocations allowed) ----
__device__ float g_xT[(size_t)B_ * D_ * L_];   // [B][D][L]
__device__ float g_UT[(size_t)D_ * Y_];        // [D][Y]
__device__ float g_FT[(size_t)D_ * Y_];        // [D][Y]
__device__ float g_y[(size_t)B_ * Y_];         // logits [B][Y]
__device__ float g_loss;

// ============================================================
// Batched 32x32 tiled transpose: in[b][r][c] -> out[b][c][r]
// which: 0 -> g_xT, 1 -> g_UT, 2 -> g_FT
// ============================================================
__global__ void transpose_kernel(const float* __restrict__ in, int R, int C, int which) {
    __shared__ float tile[32][33];
    float* out = (which == 0) ? g_xT : (which == 1) ? g_UT : g_FT;
    int b = blockIdx.z;
    const float* src = in + (size_t)b * R * C;
    float* dst = out + (size_t)b * R * C;
    int r0 = blockIdx.y * 32, c0 = blockIdx.x * 32;
#pragma unroll
    for (int i = 0; i < 32; i += 8)
        tile[threadIdx.y + i][threadIdx.x] =
            src[(size_t)(r0 + threadIdx.y + i) * C + (c0 + threadIdx.x)];
    __syncthreads();
#pragma unroll
    for (int i = 0; i < 32; i += 8)
        dst[(size_t)(c0 + threadIdx.y + i) * R + (r0 + threadIdx.x)] =
            tile[threadIdx.x][threadIdx.y + i];
}

// ============================================================
// Fused dual-GEMM + online softmax kernel
// ============================================================
#define TY 64
#define TL 64
#define KC 32
#define LDP 68                 // smem row stride (floats): 16B-aligned, conflict-free
#define NKC (D_ / KC)          // 24
#define NLT (L_ / TL)          // 64

__device__ __forceinline__ unsigned long long pack2(float x) {
    unsigned long long r;
    unsigned int u = __float_as_uint(x);
    asm("mov.b64 %0, {%1, %1};" : "=l"(r) : "r"(u));
    return r;
}
#define FFMA2(acc, a, b) \
    asm("fma.rn.f32x2 %0, %1, %2, %0;" : "+l"(acc) : "l"(a), "l"(b))

__device__ __forceinline__ float rmax16(float v) {
#pragma unroll
    for (int s = 8; s > 0; s >>= 1) v = fmaxf(v, __shfl_xor_sync(0xffffffffu, v, s));
    return v;
}
__device__ __forceinline__ float rsum16(float v) {
#pragma unroll
    for (int s = 8; s > 0; s >>= 1) v += __shfl_xor_sync(0xffffffffu, v, s);
    return v;
}

__global__ void __launch_bounds__(256, 2)
fused_attention_kernel(const float* __restrict__ bias) {
    __shared__ __align__(16) float sU[KC][LDP];
    __shared__ __align__(16) float sF[KC][LDP];
    __shared__ __align__(16) float sX[KC][LDP];

    const int tid = threadIdx.x;
    const int tx = tid & 15;        // l-direction (16)
    const int ty = tid >> 4;        // y-direction (16)
    const int b = blockIdx.y;
    const int y0 = blockIdx.x * TY;

    const float* __restrict__ xT = g_xT + (size_t)b * D_ * L_;

    // tile-load coords: each thread moves two float4 rows per tile
    const int kr0 = tid >> 4;           // 0..15
    const int kr1 = (tid + 256) >> 4;   // 16..31
    const int c40 = (tid & 15) * 4;     // 0,4,...,60

    float M[4], S[4], N[4];
#pragma unroll
    for (int i = 0; i < 4; i++) { M[i] = -INFINITY; S[i] = 0.f; N[i] = 0.f; }

    for (int lt = 0; lt < NLT; lt++) {
        const int l0 = lt * TL;

        unsigned long long accA[2][4], accT[2][4];
#pragma unroll
        for (int p = 0; p < 2; p++)
#pragma unroll
            for (int j = 0; j < 4; j++) { accA[p][j] = 0ull; accT[p][j] = 0ull; }

        // prefetch X chunk 0
        float4 rX0 = *(const float4*)&xT[(size_t)kr0 * L_ + l0 + c40];
        float4 rX1 = *(const float4*)&xT[(size_t)kr1 * L_ + l0 + c40];

        for (int kc = 0; kc < NKC; kc++) {
            const int k0 = kc * KC;
            __syncthreads();
            // U/F loads (L2-hot) issued here; X was prefetched last iter
            float4 rU0 = *(const float4*)&g_UT[(size_t)(k0 + kr0) * Y_ + y0 + c40];
            float4 rU1 = *(const float4*)&g_UT[(size_t)(k0 + kr1) * Y_ + y0 + c40];
            float4 rF0 = *(const float4*)&g_FT[(size_t)(k0 + kr0) * Y_ + y0 + c40];
            float4 rF1 = *(const float4*)&g_FT[(size_t)(k0 + kr1) * Y_ + y0 + c40];
            *(float4*)&sX[kr0][c40] = rX0;
            *(float4*)&sX[kr1][c40] = rX1;
            *(float4*)&sU[kr0][c40] = rU0;
            *(float4*)&sU[kr1][c40] = rU1;
            *(float4*)&sF[kr0][c40] = rF0;
            *(float4*)&sF[kr1][c40] = rF1;
            __syncthreads();

            if (kc + 1 < NKC) {
                const int kn = (kc + 1) * KC;
                rX0 = *(const float4*)&xT[(size_t)(kn + kr0) * L_ + l0 + c40];
                rX1 = *(const float4*)&xT[(size_t)(kn + kr1) * L_ + l0 + c40];
            }

#pragma unroll 8
            for (int k = 0; k < KC; k++) {
                const ulonglong2 u2 = *(const ulonglong2*)&sU[k][ty * 4];
                const ulonglong2 f2 = *(const ulonglong2*)&sF[k][ty * 4];
                const float4 xv = *(const float4*)&sX[k][tx * 4];
                const unsigned long long x0 = pack2(xv.x), x1 = pack2(xv.y);
                const unsigned long long x2 = pack2(xv.z), x3 = pack2(xv.w);
                FFMA2(accA[0][0], u2.x, x0); FFMA2(accA[0][1], u2.x, x1);
                FFMA2(accA[0][2], u2.x, x2); FFMA2(accA[0][3], u2.x, x3);
                FFMA2(accA[1][0], u2.y, x0); FFMA2(accA[1][1], u2.y, x1);
                FFMA2(accA[1][2], u2.y, x2); FFMA2(accA[1][3], u2.y, x3);
                FFMA2(accT[0][0], f2.x, x0); FFMA2(accT[0][1], f2.x, x1);
                FFMA2(accT[0][2], f2.x, x2); FFMA2(accT[0][3], f2.x, x3);
                FFMA2(accT[1][0], f2.y, x0); FFMA2(accT[1][1], f2.y, x1);
                FFMA2(accT[1][2], f2.y, x2); FFMA2(accT[1][3], f2.y, x3);
            }
        }

        // ---- online softmax update over this l-tile ----
#pragma unroll
        for (int p = 0; p < 2; p++) {
#pragma unroll
            for (int q = 0; q < 2; q++) {
                const int i = p * 2 + q;   // local y row = ty*4 + i
                float a[4], t[4];
#pragma unroll
                for (int j = 0; j < 4; j++) {
                    unsigned long long va = accA[p][j], vt = accT[p][j];
                    a[j] = q ? __uint_as_float((unsigned)(va >> 32))
                             : __uint_as_float((unsigned)(va & 0xffffffffull));
                    t[j] = q ? __uint_as_float((unsigned)(vt >> 32))
                             : __uint_as_float((unsigned)(vt & 0xffffffffull));
                }
                float m = fmaxf(fmaxf(a[0], a[1]), fmaxf(a[2], a[3]));
                m = rmax16(m);
                const float newM = fmaxf(M[i], m);
                const float e0 = __expf(a[0] - newM), e1 = __expf(a[1] - newM);
                const float e2 = __expf(a[2] - newM), e3 = __expf(a[3] - newM);
                float sp = (e0 + e1) + (e2 + e3);
                float spt = e0 * t[0] + e1 * t[1] + e2 * t[2] + e3 * t[3];
                sp = rsum16(sp);
                spt = rsum16(spt);
                const float sc = __expf(M[i] - newM);   // 0 on first tile (M=-inf)
                S[i] = S[i] * sc + sp;
                N[i] = N[i] * sc + spt;
                M[i] = newM;
            }
        }
    }

    if (tx == 0) {
#pragma unroll
        for (int i = 0; i < 4; i++) {
            const int yy = y0 + ty * 4 + i;
            g_y[(size_t)b * Y_ + yy] = N[i] / S[i] + bias[yy];
        }
    }
}

// ============================================================
// Cross-entropy loss over logits g_y
// NOTE: target arrives as int32 (JAX silently downcasts int64 without x64)
// ============================================================
__global__ void loss_kernel(const int* __restrict__ target) {
    __shared__ float sred[256];
    const int tid = threadIdx.x;
    float total = 0.f;
    for (int b = 0; b < B_; b++) {
        const float* row = g_y + (size_t)b * Y_;
        float m = -INFINITY;
        for (int i = tid; i < Y_; i += 256) m = fmaxf(m, row[i]);
        sred[tid] = m; __syncthreads();
        for (int s = 128; s > 0; s >>= 1) {
            if (tid < s) sred[tid] = fmaxf(sred[tid], sred[tid + s]);
            __syncthreads();
        }
        m = sred[0]; __syncthreads();
        float sum = 0.f;
        for (int i = tid; i < Y_; i += 256) sum += __expf(row[i] - m);
        sred[tid] = sum; __syncthreads();
        for (int s = 128; s > 0; s >>= 1) {
            if (tid < s) sred[tid] += sred[tid + s];
            __syncthreads();
        }
        if (tid == 0) total += m + logf(sred[0]) - row[target[b]];
        __syncthreads();
    }
    if (tid == 0) g_loss = total / (float)B_;
}

// ============================================================
// Output assembly: tuple (loss, y) flattened -> d_out
// ============================================================
__global__ void writeout_kernel(float* __restrict__ out, int out_size) {
    const int idx = blockIdx.x * blockDim.x + threadIdx.x;
    const int ny = B_ * Y_;
    if (out_size >= ny + 1) {
        if (idx == 0) out[0] = g_loss;
        if (idx < ny) out[(out_size - ny) + idx] = g_y[idx];
    } else if (out_size == ny) {
        if (idx < ny) out[idx] = g_y[idx];
    } else {
        if (idx == 0 && out_size >= 1) out[0] = g_loss;
    }
}

extern "C" void kernel_launch(void* const* d_in, const int* in_sizes, int n_in,
                              void* d_out, int out_size) {
    const float* x      = (const float*)d_in[0];
    const float* U      = (const float*)d_in[1];
    const float* F      = (const float*)d_in[2];
    const float* bias   = (const float*)d_in[3];
    const int* tg       = (const int*)d_in[4];

    dim3 tb(32, 8);
    transpose_kernel<<<dim3(D_ / 32, L_ / 32, B_), tb>>>(x, L_, D_, 0);
    transpose_kernel<<<dim3(D_ / 32, Y_ / 32, 1), tb>>>(U, Y_, D_, 1);
    transpose_kernel<<<dim3(D_ / 32, Y_ / 32, 1), tb>>>(F, Y_, D_, 2);

    fused_attention_kernel<<<dim3(Y_ / TY, B_), 256>>>(bias);

    loss_kernel<<<1, 256>>>(tg);
    writeout_kernel<<<(B_ * Y_ + 255) / 256, 256>>>((float*)d_out, out_size);
}

// round 4
// speedup vs baseline: 2.7135x; 2.7135x over previous
#include <cuda_runtime.h>
#include <cuda_bf16.h>
#include <math.h>
#include <stdint.h>

#define B_ 8
#define L_ 4096
#define D_ 768
#define Y_ 2048

// ---------------- device scratch (no allocations allowed) ----------------
__device__ __nv_bfloat16 g_xh[(size_t)B_ * L_ * D_];
__device__ __nv_bfloat16 g_xl[(size_t)B_ * L_ * D_];
__device__ __nv_bfloat16 g_Uh[(size_t)Y_ * D_];
__device__ __nv_bfloat16 g_Ul[(size_t)Y_ * D_];
__device__ __nv_bfloat16 g_Fh[(size_t)Y_ * D_];
__device__ __nv_bfloat16 g_Fl[(size_t)Y_ * D_];
__device__ float g_att[(size_t)B_ * Y_ * L_];   // 268MB
__device__ float g_t[(size_t)B_ * Y_ * L_];     // 268MB
__device__ float g_y[(size_t)B_ * Y_];
__device__ float g_loss;

// ---------------- helpers ----------------
__device__ __forceinline__ uint32_t smem_u32(const void* p) {
    uint32_t a;
    asm("{ .reg .u64 t; cvta.to.shared.u64 t, %1; cvt.u32.u64 %0, t; }" : "=r"(a) : "l"(p));
    return a;
}
#define SWZ128(x) ((x) ^ (((x) >> 3) & 0x70))

#define CP16(dst, src) \
    asm volatile("cp.async.cg.shared.global [%0], [%1], 16;" :: "r"(dst), "l"(src))
#define CPCOMMIT() asm volatile("cp.async.commit_group;" ::: "memory")
#define CPWAIT1() asm volatile("cp.async.wait_group 1;" ::: "memory")
#define CPWAIT0() asm volatile("cp.async.wait_group 0;" ::: "memory")

__device__ __forceinline__ void ldsm_x4(uint32_t* r, uint32_t addr) {
    asm volatile("ldmatrix.sync.aligned.m8n8.x4.shared.b16 {%0,%1,%2,%3}, [%4];"
        : "=r"(r[0]), "=r"(r[1]), "=r"(r[2]), "=r"(r[3]) : "r"(addr));
}
__device__ __forceinline__ void ldsm_x2(uint32_t* r, uint32_t addr) {
    asm volatile("ldmatrix.sync.aligned.m8n8.x2.shared.b16 {%0,%1}, [%2];"
        : "=r"(r[0]), "=r"(r[1]) : "r"(addr));
}
#define MMA_BF16(d, a, b)                                                     \
    asm volatile("mma.sync.aligned.m16n8k16.row.col.f32.bf16.bf16.f32 "       \
        "{%0,%1,%2,%3}, {%4,%5,%6,%7}, {%8,%9}, {%0,%1,%2,%3};"               \
        : "+f"((d)[0]), "+f"((d)[1]), "+f"((d)[2]), "+f"((d)[3])              \
        : "r"((a)[0]), "r"((a)[1]), "r"((a)[2]), "r"((a)[3]),                 \
          "r"((b)[0]), "r"((b)[1]))

// ---------------- split fp32 -> bf16 hi/lo ----------------
__global__ void split_kernel(const float* __restrict__ in,
                             __nv_bfloat16* __restrict__ hi,
                             __nv_bfloat16* __restrict__ lo, int n4) {
    int i = blockIdx.x * blockDim.x + threadIdx.x;
    if (i >= n4) return;
    float4 v = ((const float4*)in)[i];
    __nv_bfloat16 h0 = __float2bfloat16(v.x), h1 = __float2bfloat16(v.y);
    __nv_bfloat16 h2 = __float2bfloat16(v.z), h3 = __float2bfloat16(v.w);
    __nv_bfloat16 l0 = __float2bfloat16(v.x - __bfloat162float(h0));
    __nv_bfloat16 l1 = __float2bfloat16(v.y - __bfloat162float(h1));
    __nv_bfloat16 l2 = __float2bfloat16(v.z - __bfloat162float(h2));
    __nv_bfloat16 l3 = __float2bfloat16(v.w - __bfloat162float(h3));
    ((__nv_bfloat162*)hi)[i * 2 + 0] = __nv_bfloat162(h0, h1);
    ((__nv_bfloat162*)hi)[i * 2 + 1] = __nv_bfloat162(h2, h3);
    ((__nv_bfloat162*)lo)[i * 2 + 0] = __nv_bfloat162(l0, l1);
    ((__nv_bfloat162*)lo)[i * 2 + 1] = __nv_bfloat162(l2, l3);
}

// ---------------- dual GEMM: att = U.x^T, t = F.x^T (bf16 3-term split) ----
// CTA: 128y x 128l, 512 threads (16 warps). Warps 0-7: U, warps 8-15: F.
// K chunk 64 (SW128 rows of 128B), double-buffered via cp.async.
#define TILE16K 16384
#define STAGE_B 98304                    // 6 tiles * 16KB (Uh,Ul,Fh,Fl,xh,xl)
#define GSMEM (2 * STAGE_B)              // 196608

__device__ __forceinline__ void issue_stage(
    uint32_t sb, int buf, int ks, int tid,
    const __nv_bfloat16* const* srcs) {
#pragma unroll
    for (int j = 0; j < 12; j++) {
        const int gi = j * 512 + tid;
        const int t = gi >> 10;            // tile 0..5
        const int ci = gi & 1023;
        const int row = ci >> 3;           // 0..127
        const int c16 = ci & 7;            // 16B chunk in 128B row
        const char* src = (const char*)(srcs[t] + (size_t)row * D_ + ks * 64) + c16 * 16;
        const uint32_t dst = sb + buf * STAGE_B + t * TILE16K + SWZ128(row * 128 + c16 * 16);
        CP16(dst, src);
    }
    CPCOMMIT();
}

__global__ void __launch_bounds__(512, 1)
gemm_kernel() {
    extern __shared__ char smem[];
    const uint32_t sb = smem_u32(smem);
    const int tid = threadIdx.x, lane = tid & 31, wid = tid >> 5;
    const int b = blockIdx.z;
    const int y0 = blockIdx.y * 128;
    const int l0 = blockIdx.x * 128;

    const __nv_bfloat16* srcs[6] = {
        g_Uh + (size_t)y0 * D_, g_Ul + (size_t)y0 * D_,
        g_Fh + (size_t)y0 * D_, g_Fl + (size_t)y0 * D_,
        g_xh + ((size_t)b * L_ + l0) * D_, g_xl + ((size_t)b * L_ + l0) * D_
    };

    issue_stage(sb, 0, 0, tid, srcs);
    issue_stage(sb, 1, 1, tid, srcs);

    const int wg = wid & 7;
    const bool isF = (wid >= 8);
    const int my = (wg & 3) * 32;          // y offset of warp tile
    const int nl = (wg >> 2) * 64;         // l offset of warp tile
    const uint32_t aHiOff = isF ? 2 * TILE16K : 0;          // Fh : Uh
    const uint32_t aLoOff = aHiOff + TILE16K;               // Fl : Ul
    const uint32_t bHiOff = 4 * TILE16K;                    // xh
    const uint32_t bLoOff = 5 * TILE16K;                    // xl

    float acc[2][8][4];
#pragma unroll
    for (int mt = 0; mt < 2; mt++)
#pragma unroll
        for (int nt = 0; nt < 8; nt++)
#pragma unroll
            for (int r = 0; r < 4; r++) acc[mt][nt][r] = 0.f;

    for (int ks = 0; ks < 12; ks++) {
        if (ks == 11) { CPWAIT0(); } else { CPWAIT1(); }
        __syncthreads();
        const uint32_t bufo = sb + (uint32_t)(ks & 1) * STAGE_B;

#pragma unroll
        for (int kk = 0; kk < 4; kk++) {
            uint32_t ah[2][4], al[2][4];
#pragma unroll
            for (int mt = 0; mt < 2; mt++) {
                const int arow = my + mt * 16 + (lane & 15);
                const int acol = kk * 32 + ((lane >> 4) << 4);
                const uint32_t sw = SWZ128(arow * 128 + acol);
                ldsm_x4(ah[mt], bufo + aHiOff + sw);
                ldsm_x4(al[mt], bufo + aLoOff + sw);
            }
#pragma unroll
            for (int nt = 0; nt < 8; nt++) {
                const int brow = nl + nt * 8 + (lane & 7);
                const int bcol = kk * 32 + (((lane >> 3) & 1) << 4);
                const uint32_t sw = SWZ128(brow * 128 + bcol);
                uint32_t bh[2], bl[2];
                ldsm_x2(bh, bufo + bHiOff + sw);
                ldsm_x2(bl, bufo + bLoOff + sw);
#pragma unroll
                for (int mt = 0; mt < 2; mt++) {
                    MMA_BF16(acc[mt][nt], ah[mt], bh);
                    MMA_BF16(acc[mt][nt], ah[mt], bl);
                    MMA_BF16(acc[mt][nt], al[mt], bh);
                }
            }
        }
        __syncthreads();
        if (ks + 2 < 12) issue_stage(sb, ks & 1, ks + 2, tid, srcs);
    }

    // epilogue: write fp32 tiles
    float* __restrict__ out = isF ? g_t : g_att;
#pragma unroll
    for (int mt = 0; mt < 2; mt++) {
#pragma unroll
        for (int nt = 0; nt < 8; nt++) {
            const int r0 = y0 + my + mt * 16 + (lane >> 2);
            const int c = l0 + nl + nt * 8 + (lane & 3) * 2;
            float2 v0 = make_float2(acc[mt][nt][0], acc[mt][nt][1]);
            float2 v1 = make_float2(acc[mt][nt][2], acc[mt][nt][3]);
            *(float2*)&out[((size_t)b * Y_ + r0) * L_ + c] = v0;
            *(float2*)&out[((size_t)b * Y_ + r0 + 8) * L_ + c] = v1;
        }
    }
}

// ---------------- pass 2: row softmax + weighted dot ----------------
__global__ void __launch_bounds__(256)
softmax_kernel(const float* __restrict__ bias) {
    const int r = blockIdx.x;                 // b*Y + y
    const float* __restrict__ arow = g_att + (size_t)r * L_;
    const float* __restrict__ trow = g_t + (size_t)r * L_;
    const int tid = threadIdx.x;
    __shared__ float sred[256], sred2[256];

    float m = -INFINITY;
    for (int i = tid; i < L_; i += 256) m = fmaxf(m, arow[i]);
    sred[tid] = m; __syncthreads();
    for (int s = 128; s > 0; s >>= 1) {
        if (tid < s) sred[tid] = fmaxf(sred[tid], sred[tid + s]);
        __syncthreads();
    }
    m = sred[0]; __syncthreads();

    float S = 0.f, N = 0.f;
    for (int i = tid; i < L_; i += 256) {
        const float e = __expf(arow[i] - m);
        S += e;
        N += e * trow[i];
    }
    sred[tid] = S; sred2[tid] = N; __syncthreads();
    for (int s = 128; s > 0; s >>= 1) {
        if (tid < s) { sred[tid] += sred[tid + s]; sred2[tid] += sred2[tid + s]; }
        __syncthreads();
    }
    if (tid == 0) g_y[r] = sred2[0] / sred[0] + bias[r & (Y_ - 1)];
}

// ---------------- cross-entropy loss (target arrives int32) --------------
__global__ void loss_kernel(const int* __restrict__ target) {
    __shared__ float sred[256];
    const int tid = threadIdx.x;
    float total = 0.f;
    for (int b = 0; b < B_; b++) {
        const float* row = g_y + (size_t)b * Y_;
        float m = -INFINITY;
        for (int i = tid; i < Y_; i += 256) m = fmaxf(m, row[i]);
        sred[tid] = m; __syncthreads();
        for (int s = 128; s > 0; s >>= 1) {
            if (tid < s) sred[tid] = fmaxf(sred[tid], sred[tid + s]);
            __syncthreads();
        }
        m = sred[0]; __syncthreads();
        float sum = 0.f;
        for (int i = tid; i < Y_; i += 256) sum += __expf(row[i] - m);
        sred[tid] = sum; __syncthreads();
        for (int s = 128; s > 0; s >>= 1) {
            if (tid < s) sred[tid] += sred[tid + s];
            __syncthreads();
        }
        if (tid == 0) total += m + logf(sred[0]) - row[target[b]];
        __syncthreads();
    }
    if (tid == 0) g_loss = total / (float)B_;
}

__global__ void writeout_kernel(float* __restrict__ out, int out_size) {
    const int idx = blockIdx.x * blockDim.x + threadIdx.x;
    const int ny = B_ * Y_;
    if (out_size >= ny + 1) {
        if (idx == 0) out[0] = g_loss;
        if (idx < ny) out[(out_size - ny) + idx] = g_y[idx];
    } else if (out_size == ny) {
        if (idx < ny) out[idx] = g_y[idx];
    } else {
        if (idx == 0 && out_size >= 1) out[0] = g_loss;
    }
}

extern "C" void kernel_launch(void* const* d_in, const int* in_sizes, int n_in,
                              void* d_out, int out_size) {
    const float* x    = (const float*)d_in[0];
    const float* U    = (const float*)d_in[1];
    const float* F    = (const float*)d_in[2];
    const float* bias = (const float*)d_in[3];
    const int*   tg   = (const int*)d_in[4];

    void *xh, *xl, *Uh, *Ul, *Fh, *Fl;
    cudaGetSymbolAddress(&xh, g_xh); cudaGetSymbolAddress(&xl, g_xl);
    cudaGetSymbolAddress(&Uh, g_Uh); cudaGetSymbolAddress(&Ul, g_Ul);
    cudaGetSymbolAddress(&Fh, g_Fh); cudaGetSymbolAddress(&Fl, g_Fl);

    const int nx4 = B_ * L_ * D_ / 4;
    const int nw4 = Y_ * D_ / 4;
    split_kernel<<<(nx4 + 255) / 256, 256>>>(x, (__nv_bfloat16*)xh, (__nv_bfloat16*)xl, nx4);
    split_kernel<<<(nw4 + 255) / 256, 256>>>(U, (__nv_bfloat16*)Uh, (__nv_bfloat16*)Ul, nw4);
    split_kernel<<<(nw4 + 255) / 256, 256>>>(F, (__nv_bfloat16*)Fh, (__nv_bfloat16*)Fl, nw4);

    cudaFuncSetAttribute(gemm_kernel, cudaFuncAttributeMaxDynamicSharedMemorySize, GSMEM);
    gemm_kernel<<<dim3(L_ / 128, Y_ / 128, B_), 512, GSMEM>>>();

    softmax_kernel<<<B_ * Y_, 256>>>(bias);
    loss_kernel<<<1, 256>>>(tg);
    writeout_kernel<<<(B_ * Y_ + 255) / 256, 256>>>((float*)d_out, out_size);
}

// round 6
// speedup vs baseline: 3.0545x; 1.1257x over previous
#include <cuda_runtime.h>
#include <cuda_bf16.h>
#include <math.h>
#include <stdint.h>

#define B_ 8
#define L_ 4096
#define D_ 768
#define Y_ 2048

// ---------------- device scratch (no allocations allowed) ----------------
__device__ __nv_bfloat16 g_xh[(size_t)B_ * L_ * D_];
__device__ __nv_bfloat16 g_xl[(size_t)B_ * L_ * D_];
__device__ __nv_bfloat16 g_Uh[(size_t)Y_ * D_];
__device__ __nv_bfloat16 g_Ul[(size_t)Y_ * D_];
__device__ __nv_bfloat16 g_Fh[(size_t)Y_ * D_];
__device__ __nv_bfloat16 g_Fl[(size_t)Y_ * D_];
__device__ float g_att[(size_t)B_ * Y_ * L_];
__device__ float g_t[(size_t)B_ * Y_ * L_];
__device__ float g_rowmax[(size_t)B_ * Y_];
__device__ float g_y[(size_t)B_ * Y_];
__device__ float g_loss;

// ---------------- helpers ----------------
__device__ __forceinline__ uint32_t smem_u32(const void* p) {
    uint32_t a;
    asm("{ .reg .u64 t; cvta.to.shared.u64 t, %1; cvt.u32.u64 %0, t; }" : "=r"(a) : "l"(p));
    return a;
}
#define SWZ128(x) ((x) ^ (((x) >> 3) & 0x70))

#define CP16(dst, src) \
    asm volatile("cp.async.cg.shared.global [%0], [%1], 16;" :: "r"(dst), "l"(src))
#define CPCOMMIT() asm volatile("cp.async.commit_group;" ::: "memory")
#define CPWAIT1() asm volatile("cp.async.wait_group 1;" ::: "memory")
#define CPWAIT0() asm volatile("cp.async.wait_group 0;" ::: "memory")

__device__ __forceinline__ void ldsm_x4(uint32_t* r, uint32_t addr) {
    asm volatile("ldmatrix.sync.aligned.m8n8.x4.shared.b16 {%0,%1,%2,%3}, [%4];"
        : "=r"(r[0]), "=r"(r[1]), "=r"(r[2]), "=r"(r[3]) : "r"(addr));
}
#define MMA_BF16(d, a, b0, b1)                                                \
    asm volatile("mma.sync.aligned.m16n8k16.row.col.f32.bf16.bf16.f32 "       \
        "{%0,%1,%2,%3}, {%4,%5,%6,%7}, {%8,%9}, {%0,%1,%2,%3};"               \
        : "+f"((d)[0]), "+f"((d)[1]), "+f"((d)[2]), "+f"((d)[3])              \
        : "r"((a)[0]), "r"((a)[1]), "r"((a)[2]), "r"((a)[3]),                 \
          "r"(b0), "r"(b1))

__device__ __forceinline__ void atomicMaxF(float* a, float v) {
    if (v >= 0.f) atomicMax((int*)a, __float_as_int(v));
    else atomicMin((unsigned int*)a, __float_as_uint(v));
}

// ---------------- split fp32 -> bf16 hi/lo ----------------
__global__ void split_kernel(const float* __restrict__ in,
                             __nv_bfloat16* __restrict__ hi,
                             __nv_bfloat16* __restrict__ lo, int n4) {
    int i = blockIdx.x * blockDim.x + threadIdx.x;
    if (i >= n4) return;
    float4 v = ((const float4*)in)[i];
    __nv_bfloat16 h0 = __float2bfloat16(v.x), h1 = __float2bfloat16(v.y);
    __nv_bfloat16 h2 = __float2bfloat16(v.z), h3 = __float2bfloat16(v.w);
    __nv_bfloat16 l0 = __float2bfloat16(v.x - __bfloat162float(h0));
    __nv_bfloat16 l1 = __float2bfloat16(v.y - __bfloat162float(h1));
    __nv_bfloat16 l2 = __float2bfloat16(v.z - __bfloat162float(h2));
    __nv_bfloat16 l3 = __float2bfloat16(v.w - __bfloat162float(h3));
    ((__nv_bfloat162*)hi)[i * 2 + 0] = __nv_bfloat162(h0, h1);
    ((__nv_bfloat162*)hi)[i * 2 + 1] = __nv_bfloat162(h2, h3);
    ((__nv_bfloat162*)lo)[i * 2 + 0] = __nv_bfloat162(l0, l1);
    ((__nv_bfloat162*)lo)[i * 2 + 1] = __nv_bfloat162(l2, l3);
}

__global__ void init_rowmax_kernel() {
    int i = blockIdx.x * blockDim.x + threadIdx.x;
    if (i < B_ * Y_) g_rowmax[i] = -INFINITY;
}

// ---------------- dual GEMM: att = U.x^T, t = F.x^T (bf16 3-term split) ----
#define TILE16K 16384
#define STAGE_B 98304
#define GSMEM (2 * STAGE_B)

__device__ __forceinline__ void issue_stage(
    uint32_t sb, int buf, int ks, int tid,
    const __nv_bfloat16* const* srcs) {
#pragma unroll
    for (int j = 0; j < 12; j++) {
        const int gi = j * 512 + tid;
        const int t = gi >> 10;
        const int ci = gi & 1023;
        const int row = ci >> 3;
        const int c16 = ci & 7;
        const char* src = (const char*)(srcs[t] + (size_t)row * D_ + ks * 64) + c16 * 16;
        const uint32_t dst = sb + buf * STAGE_B + t * TILE16K + SWZ128(row * 128 + c16 * 16);
        CP16(dst, src);
    }
    CPCOMMIT();
}

__global__ void __launch_bounds__(512, 1)
gemm_kernel() {
    extern __shared__ char smem[];
    const uint32_t sb = smem_u32(smem);
    const int tid = threadIdx.x, lane = tid & 31, wid = tid >> 5;
    const int b = blockIdx.z;
    const int y0 = blockIdx.y * 128;
    const int l0 = blockIdx.x * 128;

    const __nv_bfloat16* srcs[6] = {
        g_Uh + (size_t)y0 * D_, g_Ul + (size_t)y0 * D_,
        g_Fh + (size_t)y0 * D_, g_Fl + (size_t)y0 * D_,
        g_xh + ((size_t)b * L_ + l0) * D_, g_xl + ((size_t)b * L_ + l0) * D_
    };

    issue_stage(sb, 0, 0, tid, srcs);
    issue_stage(sb, 1, 1, tid, srcs);

    const int wg = wid & 7;
    const bool isF = (wid >= 8);
    const int my = (wg & 3) * 32;
    const int nl = (wg >> 2) * 64;
    const uint32_t aHiOff = isF ? 2 * TILE16K : 0;
    const uint32_t aLoOff = aHiOff + TILE16K;
    const uint32_t bHiOff = 4 * TILE16K;
    const uint32_t bLoOff = 5 * TILE16K;

    // UNSWIZZLED byte offsets; SWZ128 applied per load (swizzle is not additive!)
    const uint32_t aByte = (uint32_t)((my + (lane & 15)) * 128 + ((lane >> 4) << 4));
    const uint32_t bByte = (uint32_t)((nl + (lane & 7) + ((lane >> 4) & 1) * 8) * 128
                                      + (((lane >> 3) & 1) << 4));

    float acc[2][8][4];
#pragma unroll
    for (int mt = 0; mt < 2; mt++)
#pragma unroll
        for (int nt = 0; nt < 8; nt++)
#pragma unroll
            for (int r = 0; r < 4; r++) acc[mt][nt][r] = 0.f;

    for (int ks = 0; ks < 12; ks++) {
        if (ks == 11) { CPWAIT0(); } else { CPWAIT1(); }
        __syncthreads();
        const uint32_t bufo = sb + (uint32_t)(ks & 1) * STAGE_B;

#pragma unroll
        for (int kk = 0; kk < 4; kk++) {
            uint32_t ah[2][4], al[2][4];
#pragma unroll
            for (int mt = 0; mt < 2; mt++) {
                const uint32_t sw = SWZ128(aByte + (uint32_t)(mt * 16 * 128 + kk * 32));
                ldsm_x4(ah[mt], bufo + aHiOff + sw);
                ldsm_x4(al[mt], bufo + aLoOff + sw);
            }
#pragma unroll
            for (int ntp = 0; ntp < 4; ntp++) {
                const uint32_t sw = SWZ128(bByte + (uint32_t)(ntp * 16 * 128 + kk * 32));
                uint32_t bh[4], bl[4];
                ldsm_x4(bh, bufo + bHiOff + sw);
                ldsm_x4(bl, bufo + bLoOff + sw);
#pragma unroll
                for (int mt = 0; mt < 2; mt++) {
                    float* a0 = acc[mt][ntp * 2];
                    float* a1 = acc[mt][ntp * 2 + 1];
                    MMA_BF16(a0, ah[mt], bh[0], bh[1]);
                    MMA_BF16(a0, ah[mt], bl[0], bl[1]);
                    MMA_BF16(a0, al[mt], bh[0], bh[1]);
                    MMA_BF16(a1, ah[mt], bh[2], bh[3]);
                    MMA_BF16(a1, ah[mt], bl[2], bl[3]);
                    MMA_BF16(a1, al[mt], bh[2], bh[3]);
                }
            }
        }
        __syncthreads();
        if (ks + 2 < 12) issue_stage(sb, ks & 1, ks + 2, tid, srcs);
    }

    // epilogue: write fp32 tiles (+ per-row max for att)
    float* __restrict__ out = isF ? g_t : g_att;
#pragma unroll
    for (int mt = 0; mt < 2; mt++) {
        float vA = -INFINITY, vB = -INFINITY;
#pragma unroll
        for (int nt = 0; nt < 8; nt++) {
            const int r0 = y0 + my + mt * 16 + (lane >> 2);
            const int c = l0 + (nl + nt * 8 + (lane & 3) * 2);
            float2 v0 = make_float2(acc[mt][nt][0], acc[mt][nt][1]);
            float2 v1 = make_float2(acc[mt][nt][2], acc[mt][nt][3]);
            *(float2*)&out[((size_t)b * Y_ + r0) * L_ + c] = v0;
            *(float2*)&out[((size_t)b * Y_ + r0 + 8) * L_ + c] = v1;
            vA = fmaxf(vA, fmaxf(v0.x, v0.y));
            vB = fmaxf(vB, fmaxf(v1.x, v1.y));
        }
        if (!isF) {
            vA = fmaxf(vA, __shfl_xor_sync(0xffffffffu, vA, 1));
            vA = fmaxf(vA, __shfl_xor_sync(0xffffffffu, vA, 2));
            vB = fmaxf(vB, __shfl_xor_sync(0xffffffffu, vB, 1));
            vB = fmaxf(vB, __shfl_xor_sync(0xffffffffu, vB, 2));
            if ((lane & 3) == 0) {
                const int r0 = y0 + my + mt * 16 + (lane >> 2);
                atomicMaxF(&g_rowmax[(size_t)b * Y_ + r0], vA);
                atomicMaxF(&g_rowmax[(size_t)b * Y_ + r0 + 8], vB);
            }
        }
    }
}

// ---------------- pass 2: single-pass softmax + weighted dot ----------------
__global__ void __launch_bounds__(256)
softmax_kernel(const float* __restrict__ bias) {
    const int r = blockIdx.x;
    const float4* __restrict__ arow = (const float4*)(g_att + (size_t)r * L_);
    const float4* __restrict__ trow = (const float4*)(g_t + (size_t)r * L_);
    const int tid = threadIdx.x;
    const float m = g_rowmax[r];
    __shared__ float sred[256], sred2[256];

    float S = 0.f, N = 0.f;
#pragma unroll
    for (int j = 0; j < 4; j++) {
        const int i = j * 256 + tid;
        const float4 a = arow[i];
        const float4 t = trow[i];
        const float e0 = __expf(a.x - m), e1 = __expf(a.y - m);
        const float e2 = __expf(a.z - m), e3 = __expf(a.w - m);
        S += (e0 + e1) + (e2 + e3);
        N += e0 * t.x + e1 * t.y + e2 * t.z + e3 * t.w;
    }
    sred[tid] = S; sred2[tid] = N; __syncthreads();
    for (int s = 128; s > 0; s >>= 1) {
        if (tid < s) { sred[tid] += sred[tid + s]; sred2[tid] += sred2[tid + s]; }
        __syncthreads();
    }
    if (tid == 0) g_y[r] = sred2[0] / sred[0] + bias[r & (Y_ - 1)];
}

// ---------------- cross-entropy loss (target arrives int32) --------------
__global__ void loss_kernel(const int* __restrict__ target) {
    __shared__ float sred[256];
    const int tid = threadIdx.x;
    float total = 0.f;
    for (int b = 0; b < B_; b++) {
        const float* row = g_y + (size_t)b * Y_;
        float m = -INFINITY;
        for (int i = tid; i < Y_; i += 256) m = fmaxf(m, row[i]);
        sred[tid] = m; __syncthreads();
        for (int s = 128; s > 0; s >>= 1) {
            if (tid < s) sred[tid] = fmaxf(sred[tid], sred[tid + s]);
            __syncthreads();
        }
        m = sred[0]; __syncthreads();
        float sum = 0.f;
        for (int i = tid; i < Y_; i += 256) sum += __expf(row[i] - m);
        sred[tid] = sum; __syncthreads();
        for (int s = 128; s > 0; s >>= 1) {
            if (tid < s) sred[tid] += sred[tid + s];
            __syncthreads();
        }
        if (tid == 0) total += m + logf(sred[0]) - row[target[b]];
        __syncthreads();
    }
    if (tid == 0) g_loss = total / (float)B_;
}

__global__ void writeout_kernel(float* __restrict__ out, int out_size) {
    const int idx = blockIdx.x * blockDim.x + threadIdx.x;
    const int ny = B_ * Y_;
    if (out_size >= ny + 1) {
        if (idx == 0) out[0] = g_loss;
        if (idx < ny) out[(out_size - ny) + idx] = g_y[idx];
    } else if (out_size == ny) {
        if (idx < ny) out[idx] = g_y[idx];
    } else {
        if (idx == 0 && out_size >= 1) out[0] = g_loss;
    }
}

extern "C" void kernel_launch(void* const* d_in, const int* in_sizes, int n_in,
                              void* d_out, int out_size) {
    const float* x    = (const float*)d_in[0];
    const float* U    = (const float*)d_in[1];
    const float* F    = (const float*)d_in[2];
    const float* bias = (const float*)d_in[3];
    const int*   tg   = (const int*)d_in[4];

    void *xh, *xl, *Uh, *Ul, *Fh, *Fl;
    cudaGetSymbolAddress(&xh, g_xh); cudaGetSymbolAddress(&xl, g_xl);
    cudaGetSymbolAddress(&Uh, g_Uh); cudaGetSymbolAddress(&Ul, g_Ul);
    cudaGetSymbolAddress(&Fh, g_Fh); cudaGetSymbolAddress(&Fl, g_Fl);

    const int nx4 = B_ * L_ * D_ / 4;
    const int nw4 = Y_ * D_ / 4;
    split_kernel<<<(nx4 + 255) / 256, 256>>>(x, (__nv_bfloat16*)xh, (__nv_bfloat16*)xl, nx4);
    split_kernel<<<(nw4 + 255) / 256, 256>>>(U, (__nv_bfloat16*)Uh, (__nv_bfloat16*)Ul, nw4);
    split_kernel<<<(nw4 + 255) / 256, 256>>>(F, (__nv_bfloat16*)Fh, (__nv_bfloat16*)Fl, nw4);
    init_rowmax_kernel<<<(B_ * Y_ + 255) / 256, 256>>>();

    cudaFuncSetAttribute(gemm_kernel, cudaFuncAttributeMaxDynamicSharedMemorySize, GSMEM);
    gemm_kernel<<<dim3(L_ / 128, Y_ / 128, B_), 512, GSMEM>>>();

    softmax_kernel<<<B_ * Y_, 256>>>(bias);
    loss_kernel<<<1, 256>>>(tg);
    writeout_kernel<<<(B_ * Y_ + 255) / 256, 256>>>((float*)d_out, out_size);
}

// round 7
// speedup vs baseline: 3.2228x; 1.0551x over previous
#include <cuda_runtime.h>
#include <cuda_bf16.h>
#include <math.h>
#include <stdint.h>

#define B_ 8
#define L_ 4096
#define D_ 768
#define Y_ 2048
#define NLB 32                 // number of l-blocks (L/128)

// ---------------- device scratch (no allocations allowed) ----------------
__device__ __nv_bfloat16 g_xh[(size_t)B_ * L_ * D_];
__device__ __nv_bfloat16 g_xl[(size_t)B_ * L_ * D_];
__device__ __nv_bfloat16 g_Uh[(size_t)Y_ * D_];
__device__ __nv_bfloat16 g_Ul[(size_t)Y_ * D_];
__device__ __nv_bfloat16 g_Fh[(size_t)Y_ * D_];
__device__ __nv_bfloat16 g_Fl[(size_t)Y_ * D_];
__device__ float g_pm[(size_t)B_ * Y_ * NLB];   // partial max
__device__ float g_ps[(size_t)B_ * Y_ * NLB];   // partial sum
__device__ float g_pn[(size_t)B_ * Y_ * NLB];   // partial numerator
__device__ float g_y[(size_t)B_ * Y_];
__device__ float g_loss;

// ---------------- helpers ----------------
__device__ __forceinline__ uint32_t smem_u32(const void* p) {
    uint32_t a;
    asm("{ .reg .u64 t; cvta.to.shared.u64 t, %1; cvt.u32.u64 %0, t; }" : "=r"(a) : "l"(p));
    return a;
}
#define SWZ128(x) ((x) ^ (((x) >> 3) & 0x70))

#define CP16(dst, src) \
    asm volatile("cp.async.cg.shared.global [%0], [%1], 16;" :: "r"(dst), "l"(src))
#define CPCOMMIT() asm volatile("cp.async.commit_group;" ::: "memory")
#define CPWAIT1() asm volatile("cp.async.wait_group 1;" ::: "memory")
#define CPWAIT0() asm volatile("cp.async.wait_group 0;" ::: "memory")

__device__ __forceinline__ void ldsm_x4(uint32_t* r, uint32_t addr) {
    asm volatile("ldmatrix.sync.aligned.m8n8.x4.shared.b16 {%0,%1,%2,%3}, [%4];"
        : "=r"(r[0]), "=r"(r[1]), "=r"(r[2]), "=r"(r[3]) : "r"(addr));
}
#define MMA_BF16(d, a, b0, b1)                                                \
    asm volatile("mma.sync.aligned.m16n8k16.row.col.f32.bf16.bf16.f32 "       \
        "{%0,%1,%2,%3}, {%4,%5,%6,%7}, {%8,%9}, {%0,%1,%2,%3};"               \
        : "+f"((d)[0]), "+f"((d)[1]), "+f"((d)[2]), "+f"((d)[3])              \
        : "r"((a)[0]), "r"((a)[1]), "r"((a)[2]), "r"((a)[3]),                 \
          "r"(b0), "r"(b1))

// ---------------- split fp32 -> bf16 hi/lo ----------------
__global__ void split_kernel(const float* __restrict__ in,
                             __nv_bfloat16* __restrict__ hi,
                             __nv_bfloat16* __restrict__ lo, int n4) {
    int i = blockIdx.x * blockDim.x + threadIdx.x;
    if (i >= n4) return;
    float4 v = ((const float4*)in)[i];
    __nv_bfloat16 h0 = __float2bfloat16(v.x), h1 = __float2bfloat16(v.y);
    __nv_bfloat16 h2 = __float2bfloat16(v.z), h3 = __float2bfloat16(v.w);
    __nv_bfloat16 l0 = __float2bfloat16(v.x - __bfloat162float(h0));
    __nv_bfloat16 l1 = __float2bfloat16(v.y - __bfloat162float(h1));
    __nv_bfloat16 l2 = __float2bfloat16(v.z - __bfloat162float(h2));
    __nv_bfloat16 l3 = __float2bfloat16(v.w - __bfloat162float(h3));
    ((__nv_bfloat162*)hi)[i * 2 + 0] = __nv_bfloat162(h0, h1);
    ((__nv_bfloat162*)hi)[i * 2 + 1] = __nv_bfloat162(h2, h3);
    ((__nv_bfloat162*)lo)[i * 2 + 0] = __nv_bfloat162(l0, l1);
    ((__nv_bfloat162*)lo)[i * 2 + 1] = __nv_bfloat162(l2, l3);
}

// ---------------- dual GEMM + in-CTA partial softmax ----------------
#define TILE16K 16384
#define STAGE_B 98304
#define EPI_STRIDE 132
#define GSMEM (2 * STAGE_B)     // 196608; epilogue needs 2*128*132*4 = 135168

__device__ __forceinline__ void issue_stage(
    uint32_t sb, int buf, int ks, int tid,
    const __nv_bfloat16* const* srcs) {
#pragma unroll
    for (int j = 0; j < 12; j++) {
        const int gi = j * 512 + tid;
        const int t = gi >> 10;
        const int ci = gi & 1023;
        const int row = ci >> 3;
        const int c16 = ci & 7;
        const char* src = (const char*)(srcs[t] + (size_t)row * D_ + ks * 64) + c16 * 16;
        const uint32_t dst = sb + buf * STAGE_B + t * TILE16K + SWZ128(row * 128 + c16 * 16);
        CP16(dst, src);
    }
    CPCOMMIT();
}

__global__ void __launch_bounds__(512, 1)
gemm_kernel() {
    extern __shared__ char smem[];
    const uint32_t sb = smem_u32(smem);
    const int tid = threadIdx.x, lane = tid & 31, wid = tid >> 5;
    const int b = blockIdx.z;
    const int y0 = blockIdx.y * 128;
    const int l0 = blockIdx.x * 128;

    const __nv_bfloat16* srcs[6] = {
        g_Uh + (size_t)y0 * D_, g_Ul + (size_t)y0 * D_,
        g_Fh + (size_t)y0 * D_, g_Fl + (size_t)y0 * D_,
        g_xh + ((size_t)b * L_ + l0) * D_, g_xl + ((size_t)b * L_ + l0) * D_
    };

    issue_stage(sb, 0, 0, tid, srcs);
    issue_stage(sb, 1, 1, tid, srcs);

    const int wg = wid & 7;
    const bool isF = (wid >= 8);
    const int my = (wg & 3) * 32;
    const int nl = (wg >> 2) * 64;
    const uint32_t aHiOff = isF ? 2 * TILE16K : 0;
    const uint32_t aLoOff = aHiOff + TILE16K;
    const uint32_t bHiOff = 4 * TILE16K;
    const uint32_t bLoOff = 5 * TILE16K;

    // UNSWIZZLED byte offsets; SWZ128 applied per load (swizzle is not additive!)
    const uint32_t aByte = (uint32_t)((my + (lane & 15)) * 128 + ((lane >> 4) << 4));
    const uint32_t bByte = (uint32_t)((nl + (lane & 7) + ((lane >> 4) & 1) * 8) * 128
                                      + (((lane >> 3) & 1) << 4));

    float acc[2][8][4];
#pragma unroll
    for (int mt = 0; mt < 2; mt++)
#pragma unroll
        for (int nt = 0; nt < 8; nt++)
#pragma unroll
            for (int r = 0; r < 4; r++) acc[mt][nt][r] = 0.f;

    for (int ks = 0; ks < 12; ks++) {
        if (ks == 11) { CPWAIT0(); } else { CPWAIT1(); }
        __syncthreads();
        const uint32_t bufo = sb + (uint32_t)(ks & 1) * STAGE_B;

#pragma unroll
        for (int kk = 0; kk < 4; kk++) {
            uint32_t ah[2][4], al[2][4];
#pragma unroll
            for (int mt = 0; mt < 2; mt++) {
                const uint32_t sw = SWZ128(aByte + (uint32_t)(mt * 16 * 128 + kk * 32));
                ldsm_x4(ah[mt], bufo + aHiOff + sw);
                ldsm_x4(al[mt], bufo + aLoOff + sw);
            }
#pragma unroll
            for (int ntp = 0; ntp < 4; ntp++) {
                const uint32_t sw = SWZ128(bByte + (uint32_t)(ntp * 16 * 128 + kk * 32));
                uint32_t bh[4], bl[4];
                ldsm_x4(bh, bufo + bHiOff + sw);
                ldsm_x4(bl, bufo + bLoOff + sw);
#pragma unroll
                for (int mt = 0; mt < 2; mt++) {
                    float* a0 = acc[mt][ntp * 2];
                    float* a1 = acc[mt][ntp * 2 + 1];
                    MMA_BF16(a0, ah[mt], bh[0], bh[1]);
                    MMA_BF16(a0, ah[mt], bl[0], bl[1]);
                    MMA_BF16(a0, al[mt], bh[0], bh[1]);
                    MMA_BF16(a1, ah[mt], bh[2], bh[3]);
                    MMA_BF16(a1, ah[mt], bl[2], bl[3]);
                    MMA_BF16(a1, al[mt], bh[2], bh[3]);
                }
            }
        }
        __syncthreads();
        if (ks + 2 < 12) issue_stage(sb, ks & 1, ks + 2, tid, srcs);
    }

    // ---- epilogue: tiles -> smem, per-CTA partial softmax, 3 floats/row out ----
    __syncthreads();    // everyone done reading stage buffers
    float* attbuf = (float*)smem;                          // [128][EPI_STRIDE]
    float* tbuf   = (float*)smem + 128 * EPI_STRIDE;       // [128][EPI_STRIDE]
    float* outb = isF ? tbuf : attbuf;
#pragma unroll
    for (int mt = 0; mt < 2; mt++) {
#pragma unroll
        for (int nt = 0; nt < 8; nt++) {
            const int r0 = my + mt * 16 + (lane >> 2);
            const int c = nl + nt * 8 + (lane & 3) * 2;
            *(float2*)&outb[r0 * EPI_STRIDE + c] =
                make_float2(acc[mt][nt][0], acc[mt][nt][1]);
            *(float2*)&outb[(r0 + 8) * EPI_STRIDE + c] =
                make_float2(acc[mt][nt][2], acc[mt][nt][3]);
        }
    }
    __syncthreads();

    {
        const int r = tid >> 2, p = tid & 3;     // 4 threads per row
        const float* arow = attbuf + r * EPI_STRIDE;
        const float* trow = tbuf + r * EPI_STRIDE;
        float m = -INFINITY;
#pragma unroll
        for (int i = 0; i < 32; i++)
            m = fmaxf(m, arow[p * 32 + ((i + p * 8) & 31)]);
        m = fmaxf(m, __shfl_xor_sync(0xffffffffu, m, 1));
        m = fmaxf(m, __shfl_xor_sync(0xffffffffu, m, 2));
        float S = 0.f, N = 0.f;
#pragma unroll
        for (int i = 0; i < 32; i++) {
            const int c = p * 32 + ((i + p * 8) & 31);
            const float e = __expf(arow[c] - m);
            S += e;
            N += e * trow[c];
        }
        S += __shfl_xor_sync(0xffffffffu, S, 1);
        S += __shfl_xor_sync(0xffffffffu, S, 2);
        N += __shfl_xor_sync(0xffffffffu, N, 1);
        N += __shfl_xor_sync(0xffffffffu, N, 2);
        if (p == 0) {
            const size_t idx = ((size_t)b * Y_ + y0 + r) * NLB + blockIdx.x;
            g_pm[idx] = m; g_ps[idx] = S; g_pn[idx] = N;
        }
    }
}

// ---------------- reduce 32 partials per row -> logits ----------------
__global__ void __launch_bounds__(256)
reduce_kernel(const float* __restrict__ bias) {
    const int rr = blockIdx.x * 8 + (threadIdx.x >> 5);   // row in [0, B*Y)
    const int lane = threadIdx.x & 31;
    const size_t base = (size_t)rr * NLB + lane;
    const float m = g_pm[base];
    float gm = m;
#pragma unroll
    for (int s = 16; s > 0; s >>= 1) gm = fmaxf(gm, __shfl_xor_sync(0xffffffffu, gm, s));
    const float sc = __expf(m - gm);
    float S = g_ps[base] * sc;
    float N = g_pn[base] * sc;
#pragma unroll
    for (int s = 16; s > 0; s >>= 1) {
        S += __shfl_xor_sync(0xffffffffu, S, s);
        N += __shfl_xor_sync(0xffffffffu, N, s);
    }
    if (lane == 0) g_y[rr] = N / S + bias[rr & (Y_ - 1)];
}

// ---------------- cross-entropy loss (target arrives int32) --------------
__global__ void loss_kernel(const int* __restrict__ target) {
    __shared__ float sred[256];
    const int tid = threadIdx.x;
    float total = 0.f;
    for (int b = 0; b < B_; b++) {
        const float* row = g_y + (size_t)b * Y_;
        float m = -INFINITY;
        for (int i = tid; i < Y_; i += 256) m = fmaxf(m, row[i]);
        sred[tid] = m; __syncthreads();
        for (int s = 128; s > 0; s >>= 1) {
            if (tid < s) sred[tid] = fmaxf(sred[tid], sred[tid + s]);
            __syncthreads();
        }
        m = sred[0]; __syncthreads();
        float sum = 0.f;
        for (int i = tid; i < Y_; i += 256) sum += __expf(row[i] - m);
        sred[tid] = sum; __syncthreads();
        for (int s = 128; s > 0; s >>= 1) {
            if (tid < s) sred[tid] += sred[tid + s];
            __syncthreads();
        }
        if (tid == 0) total += m + logf(sred[0]) - row[target[b]];
        __syncthreads();
    }
    if (tid == 0) g_loss = total / (float)B_;
}

__global__ void writeout_kernel(float* __restrict__ out, int out_size) {
    const int idx = blockIdx.x * blockDim.x + threadIdx.x;
    const int ny = B_ * Y_;
    if (out_size >= ny + 1) {
        if (idx == 0) out[0] = g_loss;
        if (idx < ny) out[(out_size - ny) + idx] = g_y[idx];
    } else if (out_size == ny) {
        if (idx < ny) out[idx] = g_y[idx];
    } else {
        if (idx == 0 && out_size >= 1) out[0] = g_loss;
    }
}

extern "C" void kernel_launch(void* const* d_in, const int* in_sizes, int n_in,
                              void* d_out, int out_size) {
    const float* x    = (const float*)d_in[0];
    const float* U    = (const float*)d_in[1];
    const float* F    = (const float*)d_in[2];
    const float* bias = (const float*)d_in[3];
    const int*   tg   = (const int*)d_in[4];

    void *xh, *xl, *Uh, *Ul, *Fh, *Fl;
    cudaGetSymbolAddress(&xh, g_xh); cudaGetSymbolAddress(&xl, g_xl);
    cudaGetSymbolAddress(&Uh, g_Uh); cudaGetSymbolAddress(&Ul, g_Ul);
    cudaGetSymbolAddress(&Fh, g_Fh); cudaGetSymbolAddress(&Fl, g_Fl);

    const int nx4 = B_ * L_ * D_ / 4;
    const int nw4 = Y_ * D_ / 4;
    split_kernel<<<(nx4 + 255) / 256, 256>>>(x, (__nv_bfloat16*)xh, (__nv_bfloat16*)xl, nx4);
    split_kernel<<<(nw4 + 255) / 256, 256>>>(U, (__nv_bfloat16*)Uh, (__nv_bfloat16*)Ul, nw4);
    split_kernel<<<(nw4 + 255) / 256, 256>>>(F, (__nv_bfloat16*)Fh, (__nv_bfloat16*)Fl, nw4);

    cudaFuncSetAttribute(gemm_kernel, cudaFuncAttributeMaxDynamicSharedMemorySize, GSMEM);
    gemm_kernel<<<dim3(L_ / 128, Y_ / 128, B_), 512, GSMEM>>>();

    reduce_kernel<<<B_ * Y_ / 8, 256>>>(bias);
    loss_kernel<<<1, 256>>>(tg);
    writeout_kernel<<<(B_ * Y_ + 255) / 256, 256>>>((float*)d_out, out_size);
}

// round 8
// speedup vs baseline: 3.4657x; 1.0754x over previous
#include <cuda_runtime.h>
#include <cuda_bf16.h>
#include <math.h>
#include <stdint.h>

#define B_ 8
#define L_ 4096
#define D_ 768
#define Y_ 2048
#define NLB 32                 // l-blocks (L/128)
#define NTILES 4096            // 32 lblk * 16 yblk * 8 b

// ---------------- device scratch (no allocations allowed) ----------------
__device__ __nv_bfloat16 g_xh[(size_t)B_ * L_ * D_];
__device__ __nv_bfloat16 g_xl[(size_t)B_ * L_ * D_];
__device__ __nv_bfloat16 g_Uh[(size_t)Y_ * D_];
__device__ __nv_bfloat16 g_Ul[(size_t)Y_ * D_];
__device__ __nv_bfloat16 g_Fh[(size_t)Y_ * D_];
__device__ __nv_bfloat16 g_Fl[(size_t)Y_ * D_];
__device__ float g_pm[(size_t)B_ * Y_ * NLB];
__device__ float g_ps[(size_t)B_ * Y_ * NLB];
__device__ float g_pn[(size_t)B_ * Y_ * NLB];
__device__ float g_y[(size_t)B_ * Y_];
__device__ float g_loss;

// ---------------- helpers ----------------
__device__ __forceinline__ uint32_t smem_u32(const void* p) {
    uint32_t a;
    asm("{ .reg .u64 t; cvta.to.shared.u64 t, %1; cvt.u32.u64 %0, t; }" : "=r"(a) : "l"(p));
    return a;
}
#define SWZ128(x) ((x) ^ (((x) >> 3) & 0x70))

#define CP16(dst, src) \
    asm volatile("cp.async.cg.shared.global [%0], [%1], 16;" :: "r"(dst), "l"(src))
#define CPCOMMIT() asm volatile("cp.async.commit_group;" ::: "memory")
#define CPWAIT1() asm volatile("cp.async.wait_group 1;" ::: "memory")
#define CPWAIT0() asm volatile("cp.async.wait_group 0;" ::: "memory")

__device__ __forceinline__ void ldsm_x4(uint32_t* r, uint32_t addr) {
    asm volatile("ldmatrix.sync.aligned.m8n8.x4.shared.b16 {%0,%1,%2,%3}, [%4];"
        : "=r"(r[0]), "=r"(r[1]), "=r"(r[2]), "=r"(r[3]) : "r"(addr));
}
#define MMA_BF16(d, a, b0, b1)                                                \
    asm volatile("mma.sync.aligned.m16n8k16.row.col.f32.bf16.bf16.f32 "       \
        "{%0,%1,%2,%3}, {%4,%5,%6,%7}, {%8,%9}, {%0,%1,%2,%3};"               \
        : "+f"((d)[0]), "+f"((d)[1]), "+f"((d)[2]), "+f"((d)[3])              \
        : "r"((a)[0]), "r"((a)[1]), "r"((a)[2]), "r"((a)[3]),                 \
          "r"(b0), "r"(b1))

// ---------------- split fp32 -> bf16 hi/lo ----------------
__global__ void split_kernel(const float* __restrict__ in,
                             __nv_bfloat16* __restrict__ hi,
                             __nv_bfloat16* __restrict__ lo, int n4) {
    int i = blockIdx.x * blockDim.x + threadIdx.x;
    if (i >= n4) return;
    float4 v = ((const float4*)in)[i];
    __nv_bfloat16 h0 = __float2bfloat16(v.x), h1 = __float2bfloat16(v.y);
    __nv_bfloat16 h2 = __float2bfloat16(v.z), h3 = __float2bfloat16(v.w);
    __nv_bfloat16 l0 = __float2bfloat16(v.x - __bfloat162float(h0));
    __nv_bfloat16 l1 = __float2bfloat16(v.y - __bfloat162float(h1));
    __nv_bfloat16 l2 = __float2bfloat16(v.z - __bfloat162float(h2));
    __nv_bfloat16 l3 = __float2bfloat16(v.w - __bfloat162float(h3));
    ((__nv_bfloat162*)hi)[i * 2 + 0] = __nv_bfloat162(h0, h1);
    ((__nv_bfloat162*)hi)[i * 2 + 1] = __nv_bfloat162(h2, h3);
    ((__nv_bfloat162*)lo)[i * 2 + 0] = __nv_bfloat162(l0, l1);
    ((__nv_bfloat162*)lo)[i * 2 + 1] = __nv_bfloat162(l2, l3);
}

// ---------------- persistent dual GEMM + register-level partial softmax ----
#define TILE16K 16384
#define STAGE_B 98304              // 6 tiles * 16KB
#define PART_OFF (2 * STAGE_B)     // 196608
#define SMEM_TOT (PART_OFF + 3 * 128 * 4 * 4)   // +6KB = 202752

// stage ls (global linear): tile = first + (ls/12)*stride, ks = ls%12
__device__ __forceinline__ void issue_stage(uint32_t sb, char* smem, int ls,
                                            int tid, int stride) {
    const int tl = ls / 12, ks = ls - tl * 12;
    const int t = blockIdx.x + tl * stride;
    const int lblk = t & 31, yblk = (t >> 5) & 15, b = t >> 9;
    const __nv_bfloat16* srcs[6] = {
        g_Uh + (size_t)(yblk * 128) * D_, g_Ul + (size_t)(yblk * 128) * D_,
        g_Fh + (size_t)(yblk * 128) * D_, g_Fl + (size_t)(yblk * 128) * D_,
        g_xh + ((size_t)b * L_ + lblk * 128) * D_,
        g_xl + ((size_t)b * L_ + lblk * 128) * D_
    };
    const uint32_t bufb = (uint32_t)(ls & 1) * STAGE_B;
#pragma unroll
    for (int j = 0; j < 12; j++) {
        const int gi = j * 512 + tid;
        const int tt = gi >> 10;
        const int ci = gi & 1023;
        const int row = ci >> 3;
        const int c16 = ci & 7;
        const char* src = (const char*)(srcs[tt] + (size_t)row * D_ + ks * 64) + c16 * 16;
        const uint32_t dst = sb + bufb + tt * TILE16K + SWZ128(row * 128 + c16 * 16);
        CP16(dst, src);
    }
    CPCOMMIT();
}

__global__ void __launch_bounds__(512, 1)
gemm_kernel() {
    extern __shared__ char smem[];
    const uint32_t sb = smem_u32(smem);
    float* partm = (float*)(smem + PART_OFF);          // [128][4]
    float* parts = partm + 128 * 4;
    float* partn = parts + 128 * 4;

    const int tid = threadIdx.x, lane = tid & 31, wid = tid >> 5;
    const int stride = gridDim.x;
    const int myN = (NTILES - blockIdx.x + stride - 1) / stride;
    const int total = 12 * myN;

    const int my = (wid & 3) * 32;
    const int nl = (wid >> 2) * 32;
    const int wcol = wid >> 2;

    // unswizzled base byte offsets (swizzle applied per load)
    const uint32_t aByte = (uint32_t)((my + (lane & 15)) * 128 + ((lane >> 4) << 4));
    const uint32_t bByte = (uint32_t)((nl + (lane & 7) + ((lane >> 4) & 1) * 8) * 128
                                      + (((lane >> 3) & 1) << 4));

    float attacc[2][4][4], tacc[2][4][4];
#pragma unroll
    for (int mt = 0; mt < 2; mt++)
#pragma unroll
        for (int nt = 0; nt < 4; nt++)
#pragma unroll
            for (int r = 0; r < 4; r++) { attacc[mt][nt][r] = 0.f; tacc[mt][nt][r] = 0.f; }

    issue_stage(sb, smem, 0, tid, stride);
    if (total > 1) issue_stage(sb, smem, 1, tid, stride);

    for (int ls = 0; ls < total; ls++) {
        if (ls == total - 1) { CPWAIT0(); } else { CPWAIT1(); }
        __syncthreads();
        const uint32_t bufo = sb + (uint32_t)(ls & 1) * STAGE_B;

#pragma unroll
        for (int kk = 0; kk < 4; kk++) {
            // B fragments: x hi/lo, 2 n-tile pairs covering 32 l
            uint32_t bh0[4], bl0[4], bh1[4], bl1[4];
            {
                const uint32_t sw0 = SWZ128(bByte + (uint32_t)(kk * 32));
                const uint32_t sw1 = SWZ128(bByte + (uint32_t)(16 * 128 + kk * 32));
                ldsm_x4(bh0, bufo + 4 * TILE16K + sw0);
                ldsm_x4(bl0, bufo + 5 * TILE16K + sw0);
                ldsm_x4(bh1, bufo + 4 * TILE16K + sw1);
                ldsm_x4(bl1, bufo + 5 * TILE16K + sw1);
            }
#pragma unroll
            for (int mt = 0; mt < 2; mt++) {
                const uint32_t sw = SWZ128(aByte + (uint32_t)(mt * 16 * 128 + kk * 32));
                uint32_t uh[4], ul[4], fh[4], fl[4];
                ldsm_x4(uh, bufo + 0 * TILE16K + sw);
                ldsm_x4(ul, bufo + 1 * TILE16K + sw);
                ldsm_x4(fh, bufo + 2 * TILE16K + sw);
                ldsm_x4(fl, bufo + 3 * TILE16K + sw);
                // att += U*x (3-term bf16 split)
                MMA_BF16(attacc[mt][0], uh, bh0[0], bh0[1]);
                MMA_BF16(attacc[mt][0], uh, bl0[0], bl0[1]);
                MMA_BF16(attacc[mt][0], ul, bh0[0], bh0[1]);
                MMA_BF16(attacc[mt][1], uh, bh0[2], bh0[3]);
                MMA_BF16(attacc[mt][1], uh, bl0[2], bl0[3]);
                MMA_BF16(attacc[mt][1], ul, bh0[2], bh0[3]);
                MMA_BF16(attacc[mt][2], uh, bh1[0], bh1[1]);
                MMA_BF16(attacc[mt][2], uh, bl1[0], bl1[1]);
                MMA_BF16(attacc[mt][2], ul, bh1[0], bh1[1]);
                MMA_BF16(attacc[mt][3], uh, bh1[2], bh1[3]);
                MMA_BF16(attacc[mt][3], uh, bl1[2], bl1[3]);
                MMA_BF16(attacc[mt][3], ul, bh1[2], bh1[3]);
                // t += F*x
                MMA_BF16(tacc[mt][0], fh, bh0[0], bh0[1]);
                MMA_BF16(tacc[mt][0], fh, bl0[0], bl0[1]);
                MMA_BF16(tacc[mt][0], fl, bh0[0], bh0[1]);
                MMA_BF16(tacc[mt][1], fh, bh0[2], bh0[3]);
                MMA_BF16(tacc[mt][1], fh, bl0[2], bl0[3]);
                MMA_BF16(tacc[mt][1], fl, bh0[2], bh0[3]);
                MMA_BF16(tacc[mt][2], fh, bh1[0], bh1[1]);
                MMA_BF16(tacc[mt][2], fh, bl1[0], bl1[1]);
                MMA_BF16(tacc[mt][2], fl, bh1[0], bh1[1]);
                MMA_BF16(tacc[mt][3], fh, bh1[2], bh1[3]);
                MMA_BF16(tacc[mt][3], fh, bl1[2], bl1[3]);
                MMA_BF16(tacc[mt][3], fl, bh1[2], bh1[3]);
            }
        }
        __syncthreads();
        if (ls + 2 < total) issue_stage(sb, smem, ls + 2, tid, stride);

        if ((ls % 12) == 11) {
            // ---- epilogue: register-level partial softmax for this tile ----
            const int t = blockIdx.x + (ls / 12) * stride;
            const int lblk = t & 31, yblk = (t >> 5) & 15, b = t >> 9;
#pragma unroll
            for (int mt = 0; mt < 2; mt++) {
#pragma unroll
                for (int half = 0; half < 2; half++) {
                    float a[8], tv[8];
#pragma unroll
                    for (int nt = 0; nt < 4; nt++) {
                        a[nt * 2 + 0] = attacc[mt][nt][half * 2 + 0];
                        a[nt * 2 + 1] = attacc[mt][nt][half * 2 + 1];
                        tv[nt * 2 + 0] = tacc[mt][nt][half * 2 + 0];
                        tv[nt * 2 + 1] = tacc[mt][nt][half * 2 + 1];
                    }
                    float m = a[0];
#pragma unroll
                    for (int j = 1; j < 8; j++) m = fmaxf(m, a[j]);
                    m = fmaxf(m, __shfl_xor_sync(0xffffffffu, m, 1));
                    m = fmaxf(m, __shfl_xor_sync(0xffffffffu, m, 2));
                    float S = 0.f, N = 0.f;
#pragma unroll
                    for (int j = 0; j < 8; j++) {
                        const float e = __expf(a[j] - m);
                        S += e;
                        N += e * tv[j];
                    }
                    S += __shfl_xor_sync(0xffffffffu, S, 1);
                    S += __shfl_xor_sync(0xffffffffu, S, 2);
                    N += __shfl_xor_sync(0xffffffffu, N, 1);
                    N += __shfl_xor_sync(0xffffffffu, N, 2);
                    if ((lane & 3) == 0) {
                        const int r = my + mt * 16 + half * 8 + (lane >> 2);
                        partm[r * 4 + wcol] = m;
                        parts[r * 4 + wcol] = S;
                        partn[r * 4 + wcol] = N;
                    }
                }
            }
            __syncthreads();
            if (tid < 128) {
                const float m0 = partm[tid * 4 + 0], m1 = partm[tid * 4 + 1];
                const float m2 = partm[tid * 4 + 2], m3 = partm[tid * 4 + 3];
                const float gm = fmaxf(fmaxf(m0, m1), fmaxf(m2, m3));
                const float e0 = __expf(m0 - gm), e1 = __expf(m1 - gm);
                const float e2 = __expf(m2 - gm), e3 = __expf(m3 - gm);
                const float S = parts[tid * 4 + 0] * e0 + parts[tid * 4 + 1] * e1
                              + parts[tid * 4 + 2] * e2 + parts[tid * 4 + 3] * e3;
                const float N = partn[tid * 4 + 0] * e0 + partn[tid * 4 + 1] * e1
                              + partn[tid * 4 + 2] * e2 + partn[tid * 4 + 3] * e3;
                const size_t idx = ((size_t)b * Y_ + yblk * 128 + tid) * NLB + lblk;
                g_pm[idx] = gm; g_ps[idx] = S; g_pn[idx] = N;
            }
            // reset accumulators for next tile
#pragma unroll
            for (int mt = 0; mt < 2; mt++)
#pragma unroll
                for (int nt = 0; nt < 4; nt++)
#pragma unroll
                    for (int r = 0; r < 4; r++) {
                        attacc[mt][nt][r] = 0.f; tacc[mt][nt][r] = 0.f;
                    }
        }
    }
}

// ---------------- reduce 32 partials per row -> logits ----------------
__global__ void __launch_bounds__(256)
reduce_kernel(const float* __restrict__ bias) {
    const int rr = blockIdx.x * 8 + (threadIdx.x >> 5);
    const int lane = threadIdx.x & 31;
    const size_t base = (size_t)rr * NLB + lane;
    const float m = g_pm[base];
    float gm = m;
#pragma unroll
    for (int s = 16; s > 0; s >>= 1) gm = fmaxf(gm, __shfl_xor_sync(0xffffffffu, gm, s));
    const float sc = __expf(m - gm);
    float S = g_ps[base] * sc;
    float N = g_pn[base] * sc;
#pragma unroll
    for (int s = 16; s > 0; s >>= 1) {
        S += __shfl_xor_sync(0xffffffffu, S, s);
        N += __shfl_xor_sync(0xffffffffu, N, s);
    }
    if (lane == 0) g_y[rr] = N / S + bias[rr & (Y_ - 1)];
}

// ---------------- cross-entropy loss (target arrives int32) --------------
__global__ void loss_kernel(const int* __restrict__ target) {
    __shared__ float sred[256];
    const int tid = threadIdx.x;
    float total = 0.f;
    for (int b = 0; b < B_; b++) {
        const float* row = g_y + (size_t)b * Y_;
        float m = -INFINITY;
        for (int i = tid; i < Y_; i += 256) m = fmaxf(m, row[i]);
        sred[tid] = m; __syncthreads();
        for (int s = 128; s > 0; s >>= 1) {
            if (tid < s) sred[tid] = fmaxf(sred[tid], sred[tid + s]);
            __syncthreads();
        }
        m = sred[0]; __syncthreads();
        float sum = 0.f;
        for (int i = tid; i < Y_; i += 256) sum += __expf(row[i] - m);
        sred[tid] = sum; __syncthreads();
        for (int s = 128; s > 0; s >>= 1) {
            if (tid < s) sred[tid] += sred[tid + s];
            __syncthreads();
        }
        if (tid == 0) total += m + logf(sred[0]) - row[target[b]];
        __syncthreads();
    }
    if (tid == 0) g_loss = total / (float)B_;
}

__global__ void writeout_kernel(float* __restrict__ out, int out_size) {
    const int idx = blockIdx.x * blockDim.x + threadIdx.x;
    const int ny = B_ * Y_;
    if (out_size >= ny + 1) {
        if (idx == 0) out[0] = g_loss;
        if (idx < ny) out[(out_size - ny) + idx] = g_y[idx];
    } else if (out_size == ny) {
        if (idx < ny) out[idx] = g_y[idx];
    } else {
        if (idx == 0 && out_size >= 1) out[0] = g_loss;
    }
}

extern "C" void kernel_launch(void* const* d_in, const int* in_sizes, int n_in,
                              void* d_out, int out_size) {
    const float* x    = (const float*)d_in[0];
    const float* U    = (const float*)d_in[1];
    const float* F    = (const float*)d_in[2];
    const float* bias = (const float*)d_in[3];
    const int*   tg   = (const int*)d_in[4];

    void *xh, *xl, *Uh, *Ul, *Fh, *Fl;
    cudaGetSymbolAddress(&xh, g_xh); cudaGetSymbolAddress(&xl, g_xl);
    cudaGetSymbolAddress(&Uh, g_Uh); cudaGetSymbolAddress(&Ul, g_Ul);
    cudaGetSymbolAddress(&Fh, g_Fh); cudaGetSymbolAddress(&Fl, g_Fl);

    const int nx4 = B_ * L_ * D_ / 4;
    const int nw4 = Y_ * D_ / 4;
    split_kernel<<<(nx4 + 255) / 256, 256>>>(x, (__nv_bfloat16*)xh, (__nv_bfloat16*)xl, nx4);
    split_kernel<<<(nw4 + 255) / 256, 256>>>(U, (__nv_bfloat16*)Uh, (__nv_bfloat16*)Ul, nw4);
    split_kernel<<<(nw4 + 255) / 256, 256>>>(F, (__nv_bfloat16*)Fh, (__nv_bfloat16*)Fl, nw4);

    int nsm = 148;
    cudaDeviceGetAttribute(&nsm, cudaDevAttrMultiProcessorCount, 0);
    cudaFuncSetAttribute(gemm_kernel, cudaFuncAttributeMaxDynamicSharedMemorySize, SMEM_TOT);
    gemm_kernel<<<nsm, 512, SMEM_TOT>>>();

    reduce_kernel<<<B_ * Y_ / 8, 256>>>(bias);
    loss_kernel<<<1, 256>>>(tg);
    writeout_kernel<<<(B_ * Y_ + 255) / 256, 256>>>((float*)d_out, out_size);
}